// round 13
// baseline (speedup 1.0000x reference)
#include <cuda_runtime.h>
#include <cuda_fp16.h>
#include <cstdint>

#define M_TOT 16384
#define K_DIM 2048
#define D_DIM 2048
#define BASIS 64
#define EPSV  1e-5f

#define BM     128
#define BN     128
#define BK     64
#define STAGES 3
#define NKT    (K_DIM / BK)    // 32
#define NTHR   256

// ---------------- scratch (__device__ globals) ------------------------------
__device__ __half g_xh[(size_t)M_TOT * K_DIM];   // 64MB
__device__ __half g_wh[(size_t)D_DIM * K_DIM];   // 8MB
__device__ __half g_rh[(size_t)D_DIM * K_DIM];   // 8MB
__device__ float  g_At[BASIS * D_DIM];
__device__ float  g_gb[BASIS * D_DIM];           // gamma[d]*B[j][d]
__device__ float  g_c1[BASIS], g_c2[BASIS];
__device__ float  g_sum[M_TOT], g_sum2[M_TOT], g_dotb[M_TOT];

// ---------------- PTX helpers ----------------------------------------------
__device__ __forceinline__ uint32_t smem_u32(const void* p) {
    uint32_t a;
    asm("{ .reg .u64 t; cvta.to.shared.u64 t, %1; cvt.u32.u64 %0, t; }" : "=r"(a) : "l"(p));
    return a;
}
__device__ __forceinline__ void cp_async16(uint32_t dst, const void* src) {
    asm volatile("cp.async.cg.shared.global [%0], [%1], 16;" :: "r"(dst), "l"(src));
}
__device__ __forceinline__ void cp_commit() {
    asm volatile("cp.async.commit_group;" ::: "memory");
}
template <int N>
__device__ __forceinline__ void cp_wait() {
    asm volatile("cp.async.wait_group %0;" :: "n"(N) : "memory");
}
__device__ __forceinline__ void ldsm4(uint32_t& r0, uint32_t& r1, uint32_t& r2,
                                      uint32_t& r3, uint32_t addr) {
    asm volatile("ldmatrix.sync.aligned.m8n8.x4.shared.b16 {%0,%1,%2,%3}, [%4];"
                 : "=r"(r0), "=r"(r1), "=r"(r2), "=r"(r3) : "r"(addr));
}
__device__ __forceinline__ void mma16816(float* d, uint32_t a0, uint32_t a1,
                                         uint32_t a2, uint32_t a3,
                                         uint32_t b0, uint32_t b1) {
    asm volatile("mma.sync.aligned.m16n8k16.row.col.f32.f16.f16.f32 "
                 "{%0,%1,%2,%3}, {%4,%5,%6,%7}, {%8,%9}, {%0,%1,%2,%3};"
                 : "+f"(d[0]), "+f"(d[1]), "+f"(d[2]), "+f"(d[3])
                 : "r"(a0), "r"(a1), "r"(a2), "r"(a3), "r"(b0), "r"(b1));
}

__device__ __forceinline__ float row_scalar(int row) {
    float mean = g_sum[row] * (1.0f / D_DIM);
    float var  = g_sum2[row] * (1.0f / D_DIM) - mean * mean;
    float inv  = rsqrtf(var + EPSV);
    int j = row & (BASIS - 1);
    return inv * (g_dotb[row] - mean * g_c1[j]) + g_c2[j];
}

#define STAGE_BYTES (BM * 128 + BN * 128)           // 32768
#define SM_STATS    (STAGES * STAGE_BYTES)          // 98304
#define SM_TOTAL    (STAGES * STAGE_BYTES + 1536)   // 99840  (x2 CTAs = 195KB)

// ---------------------------------------------------------------------------
// GEMM, 2 CTAs/SM. 256 threads, 8 warps, warp tile 64x32 (wm 0..1, wn 0..3).
// MODE 0: stats path -> per-row LN partials (atomics), no C store.
// MODE 1: residual path -> out = acc + scalar(row) * At[j64]  (final result)
// Warp-staggered s-order: warp w does s = (ss + w) & 3 so LDSM bursts of the
// 4 warps per SMSP are de-correlated (acc sum order permuted, deterministic).
// ---------------------------------------------------------------------------
template <int MODE>
__global__ void __launch_bounds__(NTHR, 2)
gemm_kernel(const __half* __restrict__ X, const __half* __restrict__ Bmat,
            float* __restrict__ out) {
    extern __shared__ char smem[];
    const uint32_t sb = smem_u32(smem);
    float* sst = (float*)(smem + SM_STATS);
    const int tid  = threadIdx.x;
    const int wid  = tid >> 5;
    const int lane = tid & 31;
    const int wm   = wid >> 2;           // 0..1 -> 64 rows
    const int wn   = wid & 3;            // 0..3 -> 32 cols
    const int m0   = blockIdx.y * BM;
    const int n0   = blockIdx.x * BN;

    if (MODE == 0 && tid < 128) {
        sst[tid * 3] = 0.f; sst[tid * 3 + 1] = 0.f; sst[tid * 3 + 2] = 0.f;
    }

    auto load_stage = [&](int stage, int kt) {
        const uint32_t base = sb + stage * STAGE_BYTES;
        const int kb = kt * BK;
#pragma unroll
        for (int i = 0; i < 4; i++) {            // A: 1024 segs
            int seg = tid + i * NTHR;
            int r = seg >> 3, ch = seg & 7;
            cp_async16(base + r * 128 + ((ch ^ (r & 7)) << 4),
                       X + (size_t)(m0 + r) * K_DIM + kb + ch * 8);
        }
#pragma unroll
        for (int i = 0; i < 4; i++) {            // B: 1024 segs
            int seg = tid + i * NTHR;
            int r = seg >> 3, ch = seg & 7;
            cp_async16(base + BM * 128 + r * 128 + ((ch ^ (r & 7)) << 4),
                       Bmat + (size_t)(n0 + r) * K_DIM + kb + ch * 8);
        }
        cp_commit();
    };

    float acc[4][4][4];                  // mt 0..3 (16-row steps), j 0..3 (8-col steps)
#pragma unroll
    for (int i = 0; i < 4; i++)
#pragma unroll
        for (int j = 0; j < 4; j++)
#pragma unroll
            for (int q = 0; q < 4; q++) acc[i][j][q] = 0.f;

#pragma unroll
    for (int s = 0; s < STAGES - 1; s++) load_stage(s, s);

    for (int kt = 0; kt < NKT; kt++) {
        cp_wait<STAGES - 2>();
        __syncthreads();                 // single barrier per kt (3-stage WAR safe)

        int tn = kt + STAGES - 1;
        if (tn < NKT) load_stage(tn % STAGES, tn);
        else          cp_commit();

        const uint32_t stA = sb + (kt % STAGES) * STAGE_BYTES;
        const uint32_t stB = stA + BM * 128;

#pragma unroll
        for (int ss = 0; ss < 4; ss++) {
            const int s = (ss + wid) & 3;        // per-warp staggered order
            uint32_t a[4][4];
#pragma unroll
            for (int mt = 0; mt < 4; mt++) {
                int r  = wm * 64 + mt * 16 + (lane & 15);
                int ch = 2 * s + (lane >> 4);
                ldsm4(a[mt][0], a[mt][1], a[mt][2], a[mt][3],
                      stA + r * 128 + ((ch ^ (r & 7)) << 4));
            }
            uint32_t b[2][4];
#pragma unroll
            for (int nt = 0; nt < 2; nt++) {
                int r  = wn * 32 + nt * 16 + (lane & 7) + ((lane >> 4) << 3);
                int ch = 2 * s + ((lane >> 3) & 1);
                ldsm4(b[nt][0], b[nt][1], b[nt][2], b[nt][3],
                      stB + r * 128 + ((ch ^ (r & 7)) << 4));
            }
#pragma unroll
            for (int mt = 0; mt < 4; mt++)
#pragma unroll
                for (int nt = 0; nt < 2; nt++) {
                    mma16816(acc[mt][2 * nt],     a[mt][0], a[mt][1], a[mt][2], a[mt][3],
                             b[nt][0], b[nt][1]);
                    mma16816(acc[mt][2 * nt + 1], a[mt][0], a[mt][1], a[mt][2], a[mt][3],
                             b[nt][2], b[nt][3]);
                }
        }
    }

    if (MODE == 1) {
        // residual path: out = acc + scalar(row) * At[row%64][col]
#pragma unroll
        for (int mt = 0; mt < 4; mt++) {
            int row  = m0 + wm * 64 + mt * 16 + (lane >> 2);
            int col0 = n0 + wn * 32 + (lane & 3) * 2;
            float sc0 = row_scalar(row);
            float sc1 = row_scalar(row + 8);
            const float* at0 = g_At + (size_t)(row & (BASIS - 1)) * D_DIM + col0;
            const float* at1 = g_At + (size_t)((row + 8) & (BASIS - 1)) * D_DIM + col0;
#pragma unroll
            for (int j = 0; j < 4; j++) {
                float2 v0 = make_float2(acc[mt][j][0] + sc0 * at0[j * 8],
                                        acc[mt][j][1] + sc0 * at0[j * 8 + 1]);
                float2 v1 = make_float2(acc[mt][j][2] + sc1 * at1[j * 8],
                                        acc[mt][j][3] + sc1 * at1[j * 8 + 1]);
                *(float2*)(out + (size_t)row * D_DIM + col0 + j * 8)       = v0;
                *(float2*)(out + (size_t)(row + 8) * D_DIM + col0 + j * 8) = v1;
            }
        }
    } else {
        // stats path: per-row partials Σt, Σt², Σ t*gb
        __syncthreads();
#pragma unroll
        for (int mt = 0; mt < 4; mt++)
#pragma unroll
            for (int h = 0; h < 2; h++) {
                int rloc = wm * 64 + mt * 16 + (lane >> 2) + h * 8;
                int j64  = (m0 + rloc) & (BASIS - 1);
                const float* gbrow = g_gb + (size_t)j64 * D_DIM + n0 + wn * 32 + (lane & 3) * 2;
                float s = 0.f, s2 = 0.f, sbv = 0.f;
#pragma unroll
                for (int j = 0; j < 4; j++) {
                    float v0 = acc[mt][j][2 * h], v1 = acc[mt][j][2 * h + 1];
                    float gb0 = gbrow[j * 8], gb1 = gbrow[j * 8 + 1];
                    s  += v0 + v1;
                    s2 += v0 * v0 + v1 * v1;
                    sbv += v0 * gb0 + v1 * gb1;
                }
#pragma unroll
                for (int o = 1; o <= 2; o <<= 1) {
                    s   += __shfl_xor_sync(0xffffffffu, s, o);
                    s2  += __shfl_xor_sync(0xffffffffu, s2, o);
                    sbv += __shfl_xor_sync(0xffffffffu, sbv, o);
                }
                if ((lane & 3) == 0) {
                    atomicAdd(&sst[rloc * 3 + 0], s);
                    atomicAdd(&sst[rloc * 3 + 1], s2);
                    atomicAdd(&sst[rloc * 3 + 2], sbv);
                }
            }
        __syncthreads();
        if (tid < BM) {
            atomicAdd(&g_sum [m0 + tid], sst[tid * 3 + 0]);
            atomicAdd(&g_sum2[m0 + tid], sst[tid * 3 + 1]);
            atomicAdd(&g_dotb[m0 + tid], sst[tid * 3 + 2]);
        }
    }
}

// ---------------------------------------------------------------------------
// x convert + stats zeroing; MLP=4 (4 float4 loads in flight per thread)
#define CVT_CHUNK 4
__global__ void __launch_bounds__(256)
cvtx_zero_kernel(const float* __restrict__ src, int n4) {
    int base = (blockIdx.x * blockDim.x + threadIdx.x) * CVT_CHUNK;
    {
        int i = blockIdx.x * blockDim.x + threadIdx.x;
        if (i < M_TOT) { g_sum[i] = 0.f; g_sum2[i] = 0.f; g_dotb[i] = 0.f; }
    }
    if (base >= n4) return;
    float4 v[CVT_CHUNK];
#pragma unroll
    for (int c = 0; c < CVT_CHUNK; c++) v[c] = ((const float4*)src)[base + c];
#pragma unroll
    for (int c = 0; c < CVT_CHUNK; c++) {
        __half h[4] = {__float2half_rn(v[c].x), __float2half_rn(v[c].y),
                       __float2half_rn(v[c].z), __float2half_rn(v[c].w)};
        *(uint2*)(g_xh + (size_t)(base + c) * 4) = *(uint2*)h;
    }
}

// W and W_res convert in one launch; MLP=4
__global__ void __launch_bounds__(256)
cvtw_kernel(const float* __restrict__ W, const float* __restrict__ R, int n4) {
    int i = (blockIdx.x * blockDim.x + threadIdx.x) * CVT_CHUNK;
    int sel = i >= n4;
    int base = sel ? i - n4 : i;
    if (base >= n4) return;
    const float* src = sel ? R : W;
    __half* dst = sel ? g_rh : g_wh;
    float4 v[CVT_CHUNK];
#pragma unroll
    for (int c = 0; c < CVT_CHUNK; c++) v[c] = ((const float4*)src)[base + c];
#pragma unroll
    for (int c = 0; c < CVT_CHUNK; c++) {
        __half h[4] = {__float2half_rn(v[c].x), __float2half_rn(v[c].y),
                       __float2half_rn(v[c].z), __float2half_rn(v[c].w)};
        *(uint2*)(dst + (size_t)(base + c) * 4) = *(uint2*)h;
    }
}

// gb/c1/c2 prep + Acoeff transpose merged. One block per j (64 blocks).
__global__ void __launch_bounds__(256)
prep_kernel(const float* __restrict__ gamma, const float* __restrict__ beta,
            const float* __restrict__ Bb, const float* __restrict__ Acoeff) {
    __shared__ float sh1[8], sh2[8];
    const int j = blockIdx.x, tid = threadIdx.x;
    float c1 = 0.f, c2 = 0.f;
    for (int d = tid; d < D_DIM; d += 256) {
        float b  = Bb[j * D_DIM + d];
        float gb = gamma[d] * b;
        g_gb[j * D_DIM + d] = gb;
        c1 += gb;
        c2 += beta[d] * b;
        g_At[j * D_DIM + d] = Acoeff[d * BASIS + j];
    }
#pragma unroll
    for (int o = 16; o > 0; o >>= 1) {
        c1 += __shfl_xor_sync(0xffffffffu, c1, o);
        c2 += __shfl_xor_sync(0xffffffffu, c2, o);
    }
    int lane = tid & 31, w = tid >> 5;
    if (lane == 0) { sh1[w] = c1; sh2[w] = c2; }
    __syncthreads();
    if (tid == 0) {
        float t1 = 0.f, t2 = 0.f;
#pragma unroll
        for (int i = 0; i < 8; i++) { t1 += sh1[i]; t2 += sh2[i]; }
        g_c1[j] = t1; g_c2[j] = t2;
    }
}

// ---------------------------------------------------------------------------
extern "C" void kernel_launch(void* const* d_in, const int* in_sizes, int n_in,
                              void* d_out, int out_size) {
    const float* x      = (const float*)d_in[0];
    const float* W      = (const float*)d_in[1];
    const float* W_res  = (const float*)d_in[2];
    const float* gamma  = (const float*)d_in[3];
    const float* beta   = (const float*)d_in[4];
    const float* Acoeff = (const float*)d_in[5];
    const float* Bbasis = (const float*)d_in[6];
    float* out = (float*)d_out;

    __half *xh; cudaGetSymbolAddress((void**)&xh, g_xh);
    __half *wh; cudaGetSymbolAddress((void**)&wh, g_wh);
    __half *rh; cudaGetSymbolAddress((void**)&rh, g_rh);

    cudaFuncSetAttribute(gemm_kernel<0>,
                         cudaFuncAttributeMaxDynamicSharedMemorySize, SM_TOTAL);
    cudaFuncSetAttribute(gemm_kernel<1>,
                         cudaFuncAttributeMaxDynamicSharedMemorySize, SM_TOTAL);

    int nx4 = (M_TOT * K_DIM) / 4;
    int nw4 = (D_DIM * K_DIM) / 4;
    prep_kernel<<<BASIS, 256>>>(gamma, beta, Bbasis, Acoeff);
    cvtx_zero_kernel<<<(nx4 / CVT_CHUNK + 255) / 256, 256>>>(x, nx4);
    cvtw_kernel<<<(2 * nw4 / CVT_CHUNK + 255) / 256, 256>>>(W, W_res, nw4);

    dim3 grid(D_DIM / BN, M_TOT / BM);   // (16, 128)
    gemm_kernel<0><<<grid, NTHR, SM_TOTAL>>>(xh, wh, nullptr);   // stats
    gemm_kernel<1><<<grid, NTHR, SM_TOTAL>>>(xh, rh, out);       // fused final
}

// round 14
// speedup vs baseline: 1.0349x; 1.0349x over previous
#include <cuda_runtime.h>
#include <cuda_fp16.h>
#include <cstdint>

#define M_TOT 16384
#define K_DIM 2048
#define D_DIM 2048
#define BASIS 64
#define EPSV  1e-5f

#define BM     128
#define BN     128
#define BK     64
#define STAGES 3
#define NKT    (K_DIM / BK)    // 32
#define NTHR   256
#define NSTATS 2048            // # stats CTAs

// ---------------- scratch (__device__ globals) ------------------------------
__device__ __half g_xh[(size_t)M_TOT * K_DIM];   // 64MB
__device__ __half g_wh[(size_t)D_DIM * K_DIM];   // 8MB
__device__ __half g_rh[(size_t)D_DIM * K_DIM];   // 8MB
__device__ float  g_At[BASIS * D_DIM];
__device__ float  g_gb[BASIS * D_DIM];           // gamma[d]*B[j][d]
__device__ float  g_c1[BASIS], g_c2[BASIS];
__device__ float  g_sum[M_TOT], g_sum2[M_TOT], g_dotb[M_TOT];
__device__ int    g_done;

// ---------------- PTX helpers ----------------------------------------------
__device__ __forceinline__ uint32_t smem_u32(const void* p) {
    uint32_t a;
    asm("{ .reg .u64 t; cvta.to.shared.u64 t, %1; cvt.u32.u64 %0, t; }" : "=r"(a) : "l"(p));
    return a;
}
__device__ __forceinline__ void cp_async16(uint32_t dst, const void* src) {
    asm volatile("cp.async.cg.shared.global [%0], [%1], 16;" :: "r"(dst), "l"(src));
}
__device__ __forceinline__ void cp_commit() {
    asm volatile("cp.async.commit_group;" ::: "memory");
}
template <int N>
__device__ __forceinline__ void cp_wait() {
    asm volatile("cp.async.wait_group %0;" :: "n"(N) : "memory");
}
__device__ __forceinline__ void ldsm4(uint32_t& r0, uint32_t& r1, uint32_t& r2,
                                      uint32_t& r3, uint32_t addr) {
    asm volatile("ldmatrix.sync.aligned.m8n8.x4.shared.b16 {%0,%1,%2,%3}, [%4];"
                 : "=r"(r0), "=r"(r1), "=r"(r2), "=r"(r3) : "r"(addr));
}
__device__ __forceinline__ void mma16816(float* d, uint32_t a0, uint32_t a1,
                                         uint32_t a2, uint32_t a3,
                                         uint32_t b0, uint32_t b1) {
    asm volatile("mma.sync.aligned.m16n8k16.row.col.f32.f16.f16.f32 "
                 "{%0,%1,%2,%3}, {%4,%5,%6,%7}, {%8,%9}, {%0,%1,%2,%3};"
                 : "+f"(d[0]), "+f"(d[1]), "+f"(d[2]), "+f"(d[3])
                 : "r"(a0), "r"(a1), "r"(a2), "r"(a3), "r"(b0), "r"(b1));
}

__device__ __forceinline__ float row_scalar(int row) {
    float mean = g_sum[row] * (1.0f / D_DIM);
    float var  = g_sum2[row] * (1.0f / D_DIM) - mean * mean;
    float inv  = rsqrtf(var + EPSV);
    int j = row & (BASIS - 1);
    return inv * (g_dotb[row] - mean * g_c1[j]) + g_c2[j];
}

#define STAGE_BYTES (BM * 128 + BN * 128)           // 32768
#define SM_STATS    (STAGES * STAGE_BYTES)          // 98304
#define SM_TOTAL    (STAGES * STAGE_BYTES + 1536)   // 99840  (x2 CTAs = 195KB)

// ---------------------------------------------------------------------------
// Unified dual GEMM, one launch. grid (16, 256).
// blockIdx.y < 128  -> stats path (bids 0..2047, dispatched first):
//     per-row LN partials via atomics, then signal g_done.
// blockIdx.y >= 128 -> residual path: full mainloop, then wait g_done==2048,
//     then out = acc + scalar(row) * At[row%64].
// 2 CTAs/SM, 256 thr, 8 warps, warp tile 64x32. Single barrier per kt.
// ---------------------------------------------------------------------------
__global__ void __launch_bounds__(NTHR, 2)
gemm_fused_kernel(const __half* __restrict__ X, const __half* __restrict__ Wh,
                  const __half* __restrict__ Rh, float* __restrict__ out) {
    extern __shared__ char smem[];
    const uint32_t sb = smem_u32(smem);
    float* sst = (float*)(smem + SM_STATS);
    const int tid  = threadIdx.x;
    const int wid  = tid >> 5;
    const int lane = tid & 31;
    const int wm   = wid >> 2;           // 0..1 -> 64 rows
    const int wn   = wid & 3;            // 0..3 -> 32 cols
    const int stats = blockIdx.y < 128;
    const int m0   = (stats ? blockIdx.y : blockIdx.y - 128) * BM;
    const int n0   = blockIdx.x * BN;
    const __half* Bmat = stats ? Wh : Rh;

    if (stats && tid < 128) {
        sst[tid * 3] = 0.f; sst[tid * 3 + 1] = 0.f; sst[tid * 3 + 2] = 0.f;
    }

    auto load_stage = [&](int stage, int kt) {
        const uint32_t base = sb + stage * STAGE_BYTES;
        const int kb = kt * BK;
#pragma unroll
        for (int i = 0; i < 4; i++) {            // A: 1024 segs
            int seg = tid + i * NTHR;
            int r = seg >> 3, ch = seg & 7;
            cp_async16(base + r * 128 + ((ch ^ (r & 7)) << 4),
                       X + (size_t)(m0 + r) * K_DIM + kb + ch * 8);
        }
#pragma unroll
        for (int i = 0; i < 4; i++) {            // B: 1024 segs
            int seg = tid + i * NTHR;
            int r = seg >> 3, ch = seg & 7;
            cp_async16(base + BM * 128 + r * 128 + ((ch ^ (r & 7)) << 4),
                       Bmat + (size_t)(n0 + r) * K_DIM + kb + ch * 8);
        }
        cp_commit();
    };

    float acc[4][4][4];
#pragma unroll
    for (int i = 0; i < 4; i++)
#pragma unroll
        for (int j = 0; j < 4; j++)
#pragma unroll
            for (int q = 0; q < 4; q++) acc[i][j][q] = 0.f;

#pragma unroll
    for (int s = 0; s < STAGES - 1; s++) load_stage(s, s);

    for (int kt = 0; kt < NKT; kt++) {
        cp_wait<STAGES - 2>();
        __syncthreads();                 // single barrier per kt (3-stage WAR safe)

        int tn = kt + STAGES - 1;
        if (tn < NKT) load_stage(tn % STAGES, tn);
        else          cp_commit();

        const uint32_t stA = sb + (kt % STAGES) * STAGE_BYTES;
        const uint32_t stB = stA + BM * 128;

#pragma unroll
        for (int s = 0; s < 4; s++) {
            uint32_t a[4][4];
#pragma unroll
            for (int mt = 0; mt < 4; mt++) {
                int r  = wm * 64 + mt * 16 + (lane & 15);
                int ch = 2 * s + (lane >> 4);
                ldsm4(a[mt][0], a[mt][1], a[mt][2], a[mt][3],
                      stA + r * 128 + ((ch ^ (r & 7)) << 4));
            }
            uint32_t b[2][4];
#pragma unroll
            for (int nt = 0; nt < 2; nt++) {
                int r  = wn * 32 + nt * 16 + (lane & 7) + ((lane >> 4) << 3);
                int ch = 2 * s + ((lane >> 3) & 1);
                ldsm4(b[nt][0], b[nt][1], b[nt][2], b[nt][3],
                      stB + r * 128 + ((ch ^ (r & 7)) << 4));
            }
#pragma unroll
            for (int mt = 0; mt < 4; mt++)
#pragma unroll
                for (int nt = 0; nt < 2; nt++) {
                    mma16816(acc[mt][2 * nt],     a[mt][0], a[mt][1], a[mt][2], a[mt][3],
                             b[nt][0], b[nt][1]);
                    mma16816(acc[mt][2 * nt + 1], a[mt][0], a[mt][1], a[mt][2], a[mt][3],
                             b[nt][2], b[nt][3]);
                }
        }
    }

    if (!stats) {
        // wait for all stats CTAs (they were dispatched first; ~0 spin)
        if (tid == 0) {
            while (atomicAdd(&g_done, 0) < NSTATS) { }
            __threadfence();
        }
        __syncthreads();
#pragma unroll
        for (int mt = 0; mt < 4; mt++) {
            int row  = m0 + wm * 64 + mt * 16 + (lane >> 2);
            int col0 = n0 + wn * 32 + (lane & 3) * 2;
            float sc0 = row_scalar(row);
            float sc1 = row_scalar(row + 8);
            const float* at0 = g_At + (size_t)(row & (BASIS - 1)) * D_DIM + col0;
            const float* at1 = g_At + (size_t)((row + 8) & (BASIS - 1)) * D_DIM + col0;
#pragma unroll
            for (int j = 0; j < 4; j++) {
                float2 v0 = make_float2(acc[mt][j][0] + sc0 * at0[j * 8],
                                        acc[mt][j][1] + sc0 * at0[j * 8 + 1]);
                float2 v1 = make_float2(acc[mt][j][2] + sc1 * at1[j * 8],
                                        acc[mt][j][3] + sc1 * at1[j * 8 + 1]);
                *(float2*)(out + (size_t)row * D_DIM + col0 + j * 8)       = v0;
                *(float2*)(out + (size_t)(row + 8) * D_DIM + col0 + j * 8) = v1;
            }
        }
    } else {
        // stats path: per-row partials Σt, Σt², Σ t*gb
        __syncthreads();
#pragma unroll
        for (int mt = 0; mt < 4; mt++)
#pragma unroll
            for (int h = 0; h < 2; h++) {
                int rloc = wm * 64 + mt * 16 + (lane >> 2) + h * 8;
                int j64  = (m0 + rloc) & (BASIS - 1);
                const float* gbrow = g_gb + (size_t)j64 * D_DIM + n0 + wn * 32 + (lane & 3) * 2;
                float s = 0.f, s2 = 0.f, sbv = 0.f;
#pragma unroll
                for (int j = 0; j < 4; j++) {
                    float v0 = acc[mt][j][2 * h], v1 = acc[mt][j][2 * h + 1];
                    float gb0 = gbrow[j * 8], gb1 = gbrow[j * 8 + 1];
                    s  += v0 + v1;
                    s2 += v0 * v0 + v1 * v1;
                    sbv += v0 * gb0 + v1 * gb1;
                }
#pragma unroll
                for (int o = 1; o <= 2; o <<= 1) {
                    s   += __shfl_xor_sync(0xffffffffu, s, o);
                    s2  += __shfl_xor_sync(0xffffffffu, s2, o);
                    sbv += __shfl_xor_sync(0xffffffffu, sbv, o);
                }
                if ((lane & 3) == 0) {
                    atomicAdd(&sst[rloc * 3 + 0], s);
                    atomicAdd(&sst[rloc * 3 + 1], s2);
                    atomicAdd(&sst[rloc * 3 + 2], sbv);
                }
            }
        __syncthreads();
        if (tid < BM) {
            atomicAdd(&g_sum [m0 + tid], sst[tid * 3 + 0]);
            atomicAdd(&g_sum2[m0 + tid], sst[tid * 3 + 1]);
            atomicAdd(&g_dotb[m0 + tid], sst[tid * 3 + 2]);
            __threadfence();
        }
        __syncthreads();
        if (tid == 0) atomicAdd(&g_done, 1);
    }
}

// ---------------------------------------------------------------------------
// One conversion kernel: x, W, W_res ranges + stats/g_done zeroing. MLP=4.
#define CVT_CHUNK 4
__global__ void __launch_bounds__(256)
cvt_all_kernel(const float* __restrict__ x, const float* __restrict__ W,
               const float* __restrict__ R, int nx4, int nw4) {
    int idx = blockIdx.x * blockDim.x + threadIdx.x;
    if (idx < M_TOT) { g_sum[idx] = 0.f; g_sum2[idx] = 0.f; g_dotb[idx] = 0.f; }
    if (idx == 0) g_done = 0;
    int base = idx * CVT_CHUNK;
    const float* src; __half* dst; int off;
    if (base < nx4)                { src = x; dst = g_xh; off = base; }
    else if (base < nx4 + nw4)     { src = W; dst = g_wh; off = base - nx4; }
    else if (base < nx4 + 2 * nw4) { src = R; dst = g_rh; off = base - nx4 - nw4; }
    else return;
    float4 v[CVT_CHUNK];
#pragma unroll
    for (int c = 0; c < CVT_CHUNK; c++) v[c] = ((const float4*)src)[off + c];
#pragma unroll
    for (int c = 0; c < CVT_CHUNK; c++) {
        __half h[4] = {__float2half_rn(v[c].x), __float2half_rn(v[c].y),
                       __float2half_rn(v[c].z), __float2half_rn(v[c].w)};
        *(uint2*)(dst + (size_t)(off + c) * 4) = *(uint2*)h;
    }
}

// gb/c1/c2 prep + Acoeff transpose merged. One block per j (64 blocks).
__global__ void __launch_bounds__(256)
prep_kernel(const float* __restrict__ gamma, const float* __restrict__ beta,
            const float* __restrict__ Bb, const float* __restrict__ Acoeff) {
    __shared__ float sh1[8], sh2[8];
    const int j = blockIdx.x, tid = threadIdx.x;
    float c1 = 0.f, c2 = 0.f;
    for (int d = tid; d < D_DIM; d += 256) {
        float b  = Bb[j * D_DIM + d];
        float gb = gamma[d] * b;
        g_gb[j * D_DIM + d] = gb;
        c1 += gb;
        c2 += beta[d] * b;
        g_At[j * D_DIM + d] = Acoeff[d * BASIS + j];
    }
#pragma unroll
    for (int o = 16; o > 0; o >>= 1) {
        c1 += __shfl_xor_sync(0xffffffffu, c1, o);
        c2 += __shfl_xor_sync(0xffffffffu, c2, o);
    }
    int lane = tid & 31, w = tid >> 5;
    if (lane == 0) { sh1[w] = c1; sh2[w] = c2; }
    __syncthreads();
    if (tid == 0) {
        float t1 = 0.f, t2 = 0.f;
#pragma unroll
        for (int i = 0; i < 8; i++) { t1 += sh1[i]; t2 += sh2[i]; }
        g_c1[j] = t1; g_c2[j] = t2;
    }
}

// ---------------------------------------------------------------------------
extern "C" void kernel_launch(void* const* d_in, const int* in_sizes, int n_in,
                              void* d_out, int out_size) {
    const float* x      = (const float*)d_in[0];
    const float* W      = (const float*)d_in[1];
    const float* W_res  = (const float*)d_in[2];
    const float* gamma  = (const float*)d_in[3];
    const float* beta   = (const float*)d_in[4];
    const float* Acoeff = (const float*)d_in[5];
    const float* Bbasis = (const float*)d_in[6];
    float* out = (float*)d_out;

    __half *xh; cudaGetSymbolAddress((void**)&xh, g_xh);
    __half *wh; cudaGetSymbolAddress((void**)&wh, g_wh);
    __half *rh; cudaGetSymbolAddress((void**)&rh, g_rh);

    cudaFuncSetAttribute(gemm_fused_kernel,
                         cudaFuncAttributeMaxDynamicSharedMemorySize, SM_TOTAL);

    int nx4 = (M_TOT * K_DIM) / 4;
    int nw4 = (D_DIM * K_DIM) / 4;
    prep_kernel<<<BASIS, 256>>>(gamma, beta, Bbasis, Acoeff);
    int ncv = (nx4 + 2 * nw4) / CVT_CHUNK;
    cvt_all_kernel<<<(ncv + 255) / 256, 256>>>(x, W, W_res, nx4, nw4);

    dim3 grid(D_DIM / BN, 2 * M_TOT / BM);   // (16, 256): y<128 stats, y>=128 residual
    gemm_fused_kernel<<<grid, NTHR, SM_TOTAL>>>(xh, wh, rh, out);
}

// round 15
// speedup vs baseline: 1.0468x; 1.0115x over previous
#include <cuda_runtime.h>
#include <cuda_fp16.h>
#include <cstdint>

#define M_TOT 16384
#define K_DIM 2048
#define D_DIM 2048
#define BASIS 64
#define EPSV  1e-5f

#define BM     128
#define BN     128
#define BK     64
#define STAGES 3
#define NKT    (K_DIM / BK)    // 32
#define NTHR   256
#define NSTATS 2048            // # stats CTAs

// ---------------- scratch (__device__ globals) ------------------------------
__device__ __half g_xh[(size_t)M_TOT * K_DIM];   // 64MB
__device__ __half g_wh[(size_t)D_DIM * K_DIM];   // 8MB
__device__ __half g_rh[(size_t)D_DIM * K_DIM];   // 8MB
__device__ float  g_At[BASIS * D_DIM];
__device__ float  g_gb[BASIS * D_DIM];           // gamma[d]*B[j][d]
__device__ float  g_c1[BASIS], g_c2[BASIS];
__device__ float  g_sum[M_TOT], g_sum2[M_TOT], g_dotb[M_TOT];
__device__ int    g_done;

// ---------------- PTX helpers ----------------------------------------------
__device__ __forceinline__ uint32_t smem_u32(const void* p) {
    uint32_t a;
    asm("{ .reg .u64 t; cvta.to.shared.u64 t, %1; cvt.u32.u64 %0, t; }" : "=r"(a) : "l"(p));
    return a;
}
__device__ __forceinline__ void cp_async16(uint32_t dst, const void* src) {
    asm volatile("cp.async.cg.shared.global [%0], [%1], 16;" :: "r"(dst), "l"(src));
}
__device__ __forceinline__ void cp_commit() {
    asm volatile("cp.async.commit_group;" ::: "memory");
}
template <int N>
__device__ __forceinline__ void cp_wait() {
    asm volatile("cp.async.wait_group %0;" :: "n"(N) : "memory");
}
__device__ __forceinline__ void ldsm4(uint32_t& r0, uint32_t& r1, uint32_t& r2,
                                      uint32_t& r3, uint32_t addr) {
    asm volatile("ldmatrix.sync.aligned.m8n8.x4.shared.b16 {%0,%1,%2,%3}, [%4];"
                 : "=r"(r0), "=r"(r1), "=r"(r2), "=r"(r3) : "r"(addr));
}
__device__ __forceinline__ void mma16816(float* d, uint32_t a0, uint32_t a1,
                                         uint32_t a2, uint32_t a3,
                                         uint32_t b0, uint32_t b1) {
    asm volatile("mma.sync.aligned.m16n8k16.row.col.f32.f16.f16.f32 "
                 "{%0,%1,%2,%3}, {%4,%5,%6,%7}, {%8,%9}, {%0,%1,%2,%3};"
                 : "+f"(d[0]), "+f"(d[1]), "+f"(d[2]), "+f"(d[3])
                 : "r"(a0), "r"(a1), "r"(a2), "r"(a3), "r"(b0), "r"(b1));
}

__device__ __forceinline__ float row_scalar(int row) {
    float mean = g_sum[row] * (1.0f / D_DIM);
    float var  = g_sum2[row] * (1.0f / D_DIM) - mean * mean;
    float inv  = rsqrtf(var + EPSV);
    int j = row & (BASIS - 1);
    return inv * (g_dotb[row] - mean * g_c1[j]) + g_c2[j];
}

#define STAGE_BYTES (BM * 128 + BN * 128)           // 32768
#define SM_STATS    (STAGES * STAGE_BYTES)          // 98304
#define SM_TOTAL    (STAGES * STAGE_BYTES + 1536)   // 99840  (x2 CTAs = 195KB)

// ---------------------------------------------------------------------------
// Unified dual GEMM, one launch. grid (16, 256).
// blockIdx.y < 128  -> stats path (bids 0..2047, dispatched first):
//     per-row LN partials via atomics, then signal g_done.
// blockIdx.y >= 128 -> residual path: full mainloop, then wait g_done==2048,
//     then out = acc + scalar(row) * At[row%64].
// 2 CTAs/SM, 256 thr, 8 warps, warp tile 64x32. Single barrier per kt.
// ---------------------------------------------------------------------------
__global__ void __launch_bounds__(NTHR, 2)
gemm_fused_kernel(const __half* __restrict__ X, const __half* __restrict__ Wh,
                  const __half* __restrict__ Rh, float* __restrict__ out) {
    extern __shared__ char smem[];
    const uint32_t sb = smem_u32(smem);
    float* sst = (float*)(smem + SM_STATS);
    const int tid  = threadIdx.x;
    const int wid  = tid >> 5;
    const int lane = tid & 31;
    const int wm   = wid >> 2;           // 0..1 -> 64 rows
    const int wn   = wid & 3;            // 0..3 -> 32 cols
    const int stats = blockIdx.y < 128;
    const int m0   = (stats ? blockIdx.y : blockIdx.y - 128) * BM;
    const int n0   = blockIdx.x * BN;
    const __half* Bmat = stats ? Wh : Rh;

    if (stats && tid < 128) {
        sst[tid * 3] = 0.f; sst[tid * 3 + 1] = 0.f; sst[tid * 3 + 2] = 0.f;
    }

    auto load_stage = [&](int stage, int kt) {
        const uint32_t base = sb + stage * STAGE_BYTES;
        const int kb = kt * BK;
#pragma unroll
        for (int i = 0; i < 4; i++) {            // A: 1024 segs
            int seg = tid + i * NTHR;
            int r = seg >> 3, ch = seg & 7;
            cp_async16(base + r * 128 + ((ch ^ (r & 7)) << 4),
                       X + (size_t)(m0 + r) * K_DIM + kb + ch * 8);
        }
#pragma unroll
        for (int i = 0; i < 4; i++) {            // B: 1024 segs
            int seg = tid + i * NTHR;
            int r = seg >> 3, ch = seg & 7;
            cp_async16(base + BM * 128 + r * 128 + ((ch ^ (r & 7)) << 4),
                       Bmat + (size_t)(n0 + r) * K_DIM + kb + ch * 8);
        }
        cp_commit();
    };

    float acc[4][4][4];
#pragma unroll
    for (int i = 0; i < 4; i++)
#pragma unroll
        for (int j = 0; j < 4; j++)
#pragma unroll
            for (int q = 0; q < 4; q++) acc[i][j][q] = 0.f;

#pragma unroll
    for (int s = 0; s < STAGES - 1; s++) load_stage(s, s);

    for (int kt = 0; kt < NKT; kt++) {
        cp_wait<STAGES - 2>();
        __syncthreads();                 // single barrier per kt (3-stage WAR safe)

        int tn = kt + STAGES - 1;
        if (tn < NKT) load_stage(tn % STAGES, tn);
        else          cp_commit();

        const uint32_t stA = sb + (kt % STAGES) * STAGE_BYTES;
        const uint32_t stB = stA + BM * 128;

#pragma unroll
        for (int s = 0; s < 4; s++) {
            uint32_t a[4][4];
#pragma unroll
            for (int mt = 0; mt < 4; mt++) {
                int r  = wm * 64 + mt * 16 + (lane & 15);
                int ch = 2 * s + (lane >> 4);
                ldsm4(a[mt][0], a[mt][1], a[mt][2], a[mt][3],
                      stA + r * 128 + ((ch ^ (r & 7)) << 4));
            }
            uint32_t b[2][4];
#pragma unroll
            for (int nt = 0; nt < 2; nt++) {
                int r  = wn * 32 + nt * 16 + (lane & 7) + ((lane >> 4) << 3);
                int ch = 2 * s + ((lane >> 3) & 1);
                ldsm4(b[nt][0], b[nt][1], b[nt][2], b[nt][3],
                      stB + r * 128 + ((ch ^ (r & 7)) << 4));
            }
#pragma unroll
            for (int mt = 0; mt < 4; mt++)
#pragma unroll
                for (int nt = 0; nt < 2; nt++) {
                    mma16816(acc[mt][2 * nt],     a[mt][0], a[mt][1], a[mt][2], a[mt][3],
                             b[nt][0], b[nt][1]);
                    mma16816(acc[mt][2 * nt + 1], a[mt][0], a[mt][1], a[mt][2], a[mt][3],
                             b[nt][2], b[nt][3]);
                }
        }
    }

    if (!stats) {
        // wait for all stats CTAs (they were dispatched first; ~0 spin)
        if (tid == 0) {
            while (atomicAdd(&g_done, 0) < NSTATS) { }
            __threadfence();
        }
        __syncthreads();
#pragma unroll
        for (int mt = 0; mt < 4; mt++) {
            int row  = m0 + wm * 64 + mt * 16 + (lane >> 2);
            int col0 = n0 + wn * 32 + (lane & 3) * 2;
            float sc0 = row_scalar(row);
            float sc1 = row_scalar(row + 8);
            const float* at0 = g_At + (size_t)(row & (BASIS - 1)) * D_DIM + col0;
            const float* at1 = g_At + (size_t)((row + 8) & (BASIS - 1)) * D_DIM + col0;
#pragma unroll
            for (int j = 0; j < 4; j++) {
                float2 v0 = make_float2(acc[mt][j][0] + sc0 * at0[j * 8],
                                        acc[mt][j][1] + sc0 * at0[j * 8 + 1]);
                float2 v1 = make_float2(acc[mt][j][2] + sc1 * at1[j * 8],
                                        acc[mt][j][3] + sc1 * at1[j * 8 + 1]);
                *(float2*)(out + (size_t)row * D_DIM + col0 + j * 8)       = v0;
                *(float2*)(out + (size_t)(row + 8) * D_DIM + col0 + j * 8) = v1;
            }
        }
    } else {
        // stats path: per-row partials Σt, Σt², Σ t*gb
        __syncthreads();
#pragma unroll
        for (int mt = 0; mt < 4; mt++)
#pragma unroll
            for (int h = 0; h < 2; h++) {
                int rloc = wm * 64 + mt * 16 + (lane >> 2) + h * 8;
                int j64  = (m0 + rloc) & (BASIS - 1);
                const float* gbrow = g_gb + (size_t)j64 * D_DIM + n0 + wn * 32 + (lane & 3) * 2;
                float s = 0.f, s2 = 0.f, sbv = 0.f;
#pragma unroll
                for (int j = 0; j < 4; j++) {
                    float v0 = acc[mt][j][2 * h], v1 = acc[mt][j][2 * h + 1];
                    float gb0 = gbrow[j * 8], gb1 = gbrow[j * 8 + 1];
                    s  += v0 + v1;
                    s2 += v0 * v0 + v1 * v1;
                    sbv += v0 * gb0 + v1 * gb1;
                }
#pragma unroll
                for (int o = 1; o <= 2; o <<= 1) {
                    s   += __shfl_xor_sync(0xffffffffu, s, o);
                    s2  += __shfl_xor_sync(0xffffffffu, s2, o);
                    sbv += __shfl_xor_sync(0xffffffffu, sbv, o);
                }
                if ((lane & 3) == 0) {
                    atomicAdd(&sst[rloc * 3 + 0], s);
                    atomicAdd(&sst[rloc * 3 + 1], s2);
                    atomicAdd(&sst[rloc * 3 + 2], sbv);
                }
            }
        __syncthreads();
        if (tid < BM) {
            atomicAdd(&g_sum [m0 + tid], sst[tid * 3 + 0]);
            atomicAdd(&g_sum2[m0 + tid], sst[tid * 3 + 1]);
            atomicAdd(&g_dotb[m0 + tid], sst[tid * 3 + 2]);
            __threadfence();
        }
        __syncthreads();
        if (tid == 0) atomicAdd(&g_done, 1);
    }
}

// ---------------------------------------------------------------------------
// Single aux kernel: blocks [0,64) do prep (gb/c1/c2/At transpose);
// blocks >= 64 do x/W/W_res conversion (MLP=4) + stats/g_done zeroing.
#define CVT_CHUNK 4
#define PREP_BLKS 64
__global__ void __launch_bounds__(256)
aux_kernel(const float* __restrict__ x, const float* __restrict__ W,
           const float* __restrict__ R,
           const float* __restrict__ gamma, const float* __restrict__ beta,
           const float* __restrict__ Bb, const float* __restrict__ Acoeff,
           int nx4, int nw4) {
    const int tid = threadIdx.x;
    if (blockIdx.x < PREP_BLKS) {
        // ---- prep path ----
        __shared__ float sh1[8], sh2[8];
        const int j = blockIdx.x;
        float c1 = 0.f, c2 = 0.f;
        for (int d = tid; d < D_DIM; d += 256) {
            float b  = Bb[j * D_DIM + d];
            float gb = gamma[d] * b;
            g_gb[j * D_DIM + d] = gb;
            c1 += gb;
            c2 += beta[d] * b;
            g_At[j * D_DIM + d] = Acoeff[d * BASIS + j];
        }
#pragma unroll
        for (int o = 16; o > 0; o >>= 1) {
            c1 += __shfl_xor_sync(0xffffffffu, c1, o);
            c2 += __shfl_xor_sync(0xffffffffu, c2, o);
        }
        int lane = tid & 31, w = tid >> 5;
        if (lane == 0) { sh1[w] = c1; sh2[w] = c2; }
        __syncthreads();
        if (tid == 0) {
            float t1 = 0.f, t2 = 0.f;
#pragma unroll
            for (int i = 0; i < 8; i++) { t1 += sh1[i]; t2 += sh2[i]; }
            g_c1[j] = t1; g_c2[j] = t2;
        }
        return;
    }
    // ---- convert path ----
    int idx = (blockIdx.x - PREP_BLKS) * blockDim.x + tid;
    if (idx < M_TOT) { g_sum[idx] = 0.f; g_sum2[idx] = 0.f; g_dotb[idx] = 0.f; }
    if (idx == 0) g_done = 0;
    int base = idx * CVT_CHUNK;
    const float* src; __half* dst; int off;
    if (base < nx4)                { src = x; dst = g_xh; off = base; }
    else if (base < nx4 + nw4)     { src = W; dst = g_wh; off = base - nx4; }
    else if (base < nx4 + 2 * nw4) { src = R; dst = g_rh; off = base - nx4 - nw4; }
    else return;
    float4 v[CVT_CHUNK];
#pragma unroll
    for (int c = 0; c < CVT_CHUNK; c++) v[c] = ((const float4*)src)[off + c];
#pragma unroll
    for (int c = 0; c < CVT_CHUNK; c++) {
        __half h[4] = {__float2half_rn(v[c].x), __float2half_rn(v[c].y),
                       __float2half_rn(v[c].z), __float2half_rn(v[c].w)};
        *(uint2*)(dst + (size_t)(off + c) * 4) = *(uint2*)h;
    }
}

// ---------------------------------------------------------------------------
extern "C" void kernel_launch(void* const* d_in, const int* in_sizes, int n_in,
                              void* d_out, int out_size) {
    const float* x      = (const float*)d_in[0];
    const float* W      = (const float*)d_in[1];
    const float* W_res  = (const float*)d_in[2];
    const float* gamma  = (const float*)d_in[3];
    const float* beta   = (const float*)d_in[4];
    const float* Acoeff = (const float*)d_in[5];
    const float* Bbasis = (const float*)d_in[6];
    float* out = (float*)d_out;

    __half *xh; cudaGetSymbolAddress((void**)&xh, g_xh);
    __half *wh; cudaGetSymbolAddress((void**)&wh, g_wh);
    __half *rh; cudaGetSymbolAddress((void**)&rh, g_rh);

    cudaFuncSetAttribute(gemm_fused_kernel,
                         cudaFuncAttributeMaxDynamicSharedMemorySize, SM_TOTAL);

    int nx4 = (M_TOT * K_DIM) / 4;
    int nw4 = (D_DIM * K_DIM) / 4;
    int cvt_blocks = ((nx4 + 2 * nw4) / CVT_CHUNK + 255) / 256;
    aux_kernel<<<cvt_blocks + PREP_BLKS, 256>>>(x, W, W_res, gamma, beta,
                                                Bbasis, Acoeff, nx4, nw4);

    dim3 grid(D_DIM / BN, 2 * M_TOT / BM);   // (16, 256): y<128 stats, y>=128 residual
    gemm_fused_kernel<<<grid, NTHR, SM_TOTAL>>>(xh, wh, rh, out);
}

// round 16
// speedup vs baseline: 1.0503x; 1.0033x over previous
#include <cuda_runtime.h>
#include <cuda_fp16.h>
#include <cstdint>

#define M_TOT 16384
#define K_DIM 2048
#define D_DIM 2048
#define BASIS 64
#define EPSV  1e-5f

#define BM     128
#define BN     128
#define BK     64
#define STAGES 3
#define NKT    (K_DIM / BK)    // 32
#define NTHR   256
#define NSTATS 2048            // # stats CTAs

// ---------------- scratch (__device__ globals) ------------------------------
__device__ __half g_xh[(size_t)M_TOT * K_DIM];   // 64MB
__device__ __half g_wh[(size_t)D_DIM * K_DIM];   // 8MB
__device__ __half g_rh[(size_t)D_DIM * K_DIM];   // 8MB
__device__ float  g_At[BASIS * D_DIM];
__device__ float  g_gb[BASIS * D_DIM];           // gamma[d]*B[j][d]
__device__ float  g_c1[BASIS], g_c2[BASIS];
__device__ float  g_sum[M_TOT], g_sum2[M_TOT], g_dotb[M_TOT];
__device__ int    g_done;

// ---------------- PTX helpers ----------------------------------------------
__device__ __forceinline__ uint32_t smem_u32(const void* p) {
    uint32_t a;
    asm("{ .reg .u64 t; cvta.to.shared.u64 t, %1; cvt.u32.u64 %0, t; }" : "=r"(a) : "l"(p));
    return a;
}
__device__ __forceinline__ void cp_async16(uint32_t dst, const void* src) {
    asm volatile("cp.async.cg.shared.global [%0], [%1], 16;" :: "r"(dst), "l"(src));
}
__device__ __forceinline__ void cp_commit() {
    asm volatile("cp.async.commit_group;" ::: "memory");
}
template <int N>
__device__ __forceinline__ void cp_wait() {
    asm volatile("cp.async.wait_group %0;" :: "n"(N) : "memory");
}
// Non-volatile: ordering is enforced by data dependences (outputs feed MMAs)
// and by __syncthreads memory clobbers around stage reuse. Lets ptxas
// interleave LDSM issue into the MMA stream.
__device__ __forceinline__ void ldsm4(uint32_t& r0, uint32_t& r1, uint32_t& r2,
                                      uint32_t& r3, uint32_t addr) {
    asm("ldmatrix.sync.aligned.m8n8.x4.shared.b16 {%0,%1,%2,%3}, [%4];"
        : "=r"(r0), "=r"(r1), "=r"(r2), "=r"(r3) : "r"(addr));
}
__device__ __forceinline__ void mma16816(float* d, uint32_t a0, uint32_t a1,
                                         uint32_t a2, uint32_t a3,
                                         uint32_t b0, uint32_t b1) {
    asm volatile("mma.sync.aligned.m16n8k16.row.col.f32.f16.f16.f32 "
                 "{%0,%1,%2,%3}, {%4,%5,%6,%7}, {%8,%9}, {%0,%1,%2,%3};"
                 : "+f"(d[0]), "+f"(d[1]), "+f"(d[2]), "+f"(d[3])
                 : "r"(a0), "r"(a1), "r"(a2), "r"(a3), "r"(b0), "r"(b1));
}

__device__ __forceinline__ float row_scalar(int row) {
    float mean = g_sum[row] * (1.0f / D_DIM);
    float var  = g_sum2[row] * (1.0f / D_DIM) - mean * mean;
    float inv  = rsqrtf(var + EPSV);
    int j = row & (BASIS - 1);
    return inv * (g_dotb[row] - mean * g_c1[j]) + g_c2[j];
}

#define STAGE_BYTES (BM * 128 + BN * 128)           // 32768
#define SM_STATS    (STAGES * STAGE_BYTES)          // 98304
#define SM_TOTAL    (STAGES * STAGE_BYTES + 1536)   // 99840  (x2 CTAs = 195KB)

// ---------------------------------------------------------------------------
// Unified dual GEMM, one launch. grid (16, 256).
// blockIdx.y < 128  -> stats path (bids 0..2047, dispatched first):
//     per-row LN partials via atomics, then signal g_done.
// blockIdx.y >= 128 -> residual path: full mainloop, then wait g_done==2048,
//     then out = acc + scalar(row) * At[row%64].
// 2 CTAs/SM, 256 thr, 8 warps, warp tile 64x32. Single barrier per kt.
// ---------------------------------------------------------------------------
__global__ void __launch_bounds__(NTHR, 2)
gemm_fused_kernel(const __half* __restrict__ X, const __half* __restrict__ Wh,
                  const __half* __restrict__ Rh, float* __restrict__ out) {
    extern __shared__ char smem[];
    const uint32_t sb = smem_u32(smem);
    float* sst = (float*)(smem + SM_STATS);
    const int tid  = threadIdx.x;
    const int wid  = tid >> 5;
    const int lane = tid & 31;
    const int wm   = wid >> 2;           // 0..1 -> 64 rows
    const int wn   = wid & 3;            // 0..3 -> 32 cols
    const int stats = blockIdx.y < 128;
    const int m0   = (stats ? blockIdx.y : blockIdx.y - 128) * BM;
    const int n0   = blockIdx.x * BN;
    const __half* Bmat = stats ? Wh : Rh;

    if (stats && tid < 128) {
        sst[tid * 3] = 0.f; sst[tid * 3 + 1] = 0.f; sst[tid * 3 + 2] = 0.f;
    }

    auto load_stage = [&](int stage, int kt) {
        const uint32_t base = sb + stage * STAGE_BYTES;
        const int kb = kt * BK;
#pragma unroll
        for (int i = 0; i < 4; i++) {            // A: 1024 segs
            int seg = tid + i * NTHR;
            int r = seg >> 3, ch = seg & 7;
            cp_async16(base + r * 128 + ((ch ^ (r & 7)) << 4),
                       X + (size_t)(m0 + r) * K_DIM + kb + ch * 8);
        }
#pragma unroll
        for (int i = 0; i < 4; i++) {            // B: 1024 segs
            int seg = tid + i * NTHR;
            int r = seg >> 3, ch = seg & 7;
            cp_async16(base + BM * 128 + r * 128 + ((ch ^ (r & 7)) << 4),
                       Bmat + (size_t)(n0 + r) * K_DIM + kb + ch * 8);
        }
        cp_commit();
    };

    float acc[4][4][4];
#pragma unroll
    for (int i = 0; i < 4; i++)
#pragma unroll
        for (int j = 0; j < 4; j++)
#pragma unroll
            for (int q = 0; q < 4; q++) acc[i][j][q] = 0.f;

#pragma unroll
    for (int s = 0; s < STAGES - 1; s++) load_stage(s, s);

    for (int kt = 0; kt < NKT; kt++) {
        cp_wait<STAGES - 2>();
        __syncthreads();                 // single barrier per kt (3-stage WAR safe)

        int tn = kt + STAGES - 1;
        if (tn < NKT) load_stage(tn % STAGES, tn);
        else          cp_commit();

        const uint32_t stA = sb + (kt % STAGES) * STAGE_BYTES;
        const uint32_t stB = stA + BM * 128;

#pragma unroll
        for (int s = 0; s < 4; s++) {
            uint32_t a[4][4];
#pragma unroll
            for (int mt = 0; mt < 4; mt++) {
                int r  = wm * 64 + mt * 16 + (lane & 15);
                int ch = 2 * s + (lane >> 4);
                ldsm4(a[mt][0], a[mt][1], a[mt][2], a[mt][3],
                      stA + r * 128 + ((ch ^ (r & 7)) << 4));
            }
            uint32_t b[2][4];
#pragma unroll
            for (int nt = 0; nt < 2; nt++) {
                int r  = wn * 32 + nt * 16 + (lane & 7) + ((lane >> 4) << 3);
                int ch = 2 * s + ((lane >> 3) & 1);
                ldsm4(b[nt][0], b[nt][1], b[nt][2], b[nt][3],
                      stB + r * 128 + ((ch ^ (r & 7)) << 4));
            }
#pragma unroll
            for (int mt = 0; mt < 4; mt++)
#pragma unroll
                for (int nt = 0; nt < 2; nt++) {
                    mma16816(acc[mt][2 * nt],     a[mt][0], a[mt][1], a[mt][2], a[mt][3],
                             b[nt][0], b[nt][1]);
                    mma16816(acc[mt][2 * nt + 1], a[mt][0], a[mt][1], a[mt][2], a[mt][3],
                             b[nt][2], b[nt][3]);
                }
        }
    }

    if (!stats) {
        // wait for all stats CTAs (they were dispatched first; ~0 spin)
        if (tid == 0) {
            while (atomicAdd(&g_done, 0) < NSTATS) { }
            __threadfence();
        }
        __syncthreads();
#pragma unroll
        for (int mt = 0; mt < 4; mt++) {
            int row  = m0 + wm * 64 + mt * 16 + (lane >> 2);
            int col0 = n0 + wn * 32 + (lane & 3) * 2;
            float sc0 = row_scalar(row);
            float sc1 = row_scalar(row + 8);
            const float* at0 = g_At + (size_t)(row & (BASIS - 1)) * D_DIM + col0;
            const float* at1 = g_At + (size_t)((row + 8) & (BASIS - 1)) * D_DIM + col0;
#pragma unroll
            for (int j = 0; j < 4; j++) {
                float2 v0 = make_float2(acc[mt][j][0] + sc0 * at0[j * 8],
                                        acc[mt][j][1] + sc0 * at0[j * 8 + 1]);
                float2 v1 = make_float2(acc[mt][j][2] + sc1 * at1[j * 8],
                                        acc[mt][j][3] + sc1 * at1[j * 8 + 1]);
                *(float2*)(out + (size_t)row * D_DIM + col0 + j * 8)       = v0;
                *(float2*)(out + (size_t)(row + 8) * D_DIM + col0 + j * 8) = v1;
            }
        }
    } else {
        // stats path: per-row partials Σt, Σt², Σ t*gb
        __syncthreads();
#pragma unroll
        for (int mt = 0; mt < 4; mt++)
#pragma unroll
            for (int h = 0; h < 2; h++) {
                int rloc = wm * 64 + mt * 16 + (lane >> 2) + h * 8;
                int j64  = (m0 + rloc) & (BASIS - 1);
                const float* gbrow = g_gb + (size_t)j64 * D_DIM + n0 + wn * 32 + (lane & 3) * 2;
                float s = 0.f, s2 = 0.f, sbv = 0.f;
#pragma unroll
                for (int j = 0; j < 4; j++) {
                    float v0 = acc[mt][j][2 * h], v1 = acc[mt][j][2 * h + 1];
                    float gb0 = gbrow[j * 8], gb1 = gbrow[j * 8 + 1];
                    s  += v0 + v1;
                    s2 += v0 * v0 + v1 * v1;
                    sbv += v0 * gb0 + v1 * gb1;
                }
#pragma unroll
                for (int o = 1; o <= 2; o <<= 1) {
                    s   += __shfl_xor_sync(0xffffffffu, s, o);
                    s2  += __shfl_xor_sync(0xffffffffu, s2, o);
                    sbv += __shfl_xor_sync(0xffffffffu, sbv, o);
                }
                if ((lane & 3) == 0) {
                    atomicAdd(&sst[rloc * 3 + 0], s);
                    atomicAdd(&sst[rloc * 3 + 1], s2);
                    atomicAdd(&sst[rloc * 3 + 2], sbv);
                }
            }
        __syncthreads();
        if (tid < BM) {
            atomicAdd(&g_sum [m0 + tid], sst[tid * 3 + 0]);
            atomicAdd(&g_sum2[m0 + tid], sst[tid * 3 + 1]);
            atomicAdd(&g_dotb[m0 + tid], sst[tid * 3 + 2]);
            __threadfence();
        }
        __syncthreads();
        if (tid == 0) atomicAdd(&g_done, 1);
    }
}

// ---------------------------------------------------------------------------
// Single aux kernel: blocks [0,64) do prep (gb/c1/c2/At transpose);
// blocks >= 64 do x/W/W_res conversion (MLP=4) + stats/g_done zeroing.
#define CVT_CHUNK 4
#define PREP_BLKS 64
__global__ void __launch_bounds__(256)
aux_kernel(const float* __restrict__ x, const float* __restrict__ W,
           const float* __restrict__ R,
           const float* __restrict__ gamma, const float* __restrict__ beta,
           const float* __restrict__ Bb, const float* __restrict__ Acoeff,
           int nx4, int nw4) {
    const int tid = threadIdx.x;
    if (blockIdx.x < PREP_BLKS) {
        // ---- prep path ----
        __shared__ float sh1[8], sh2[8];
        const int j = blockIdx.x;
        float c1 = 0.f, c2 = 0.f;
        for (int d = tid; d < D_DIM; d += 256) {
            float b  = Bb[j * D_DIM + d];
            float gb = gamma[d] * b;
            g_gb[j * D_DIM + d] = gb;
            c1 += gb;
            c2 += beta[d] * b;
            g_At[j * D_DIM + d] = Acoeff[d * BASIS + j];
        }
#pragma unroll
        for (int o = 16; o > 0; o >>= 1) {
            c1 += __shfl_xor_sync(0xffffffffu, c1, o);
            c2 += __shfl_xor_sync(0xffffffffu, c2, o);
        }
        int lane = tid & 31, w = tid >> 5;
        if (lane == 0) { sh1[w] = c1; sh2[w] = c2; }
        __syncthreads();
        if (tid == 0) {
            float t1 = 0.f, t2 = 0.f;
#pragma unroll
            for (int i = 0; i < 8; i++) { t1 += sh1[i]; t2 += sh2[i]; }
            g_c1[j] = t1; g_c2[j] = t2;
        }
        return;
    }
    // ---- convert path ----
    int idx = (blockIdx.x - PREP_BLKS) * blockDim.x + tid;
    if (idx < M_TOT) { g_sum[idx] = 0.f; g_sum2[idx] = 0.f; g_dotb[idx] = 0.f; }
    if (idx == 0) g_done = 0;
    int base = idx * CVT_CHUNK;
    const float* src; __half* dst; int off;
    if (base < nx4)                { src = x; dst = g_xh; off = base; }
    else if (base < nx4 + nw4)     { src = W; dst = g_wh; off = base - nx4; }
    else if (base < nx4 + 2 * nw4) { src = R; dst = g_rh; off = base - nx4 - nw4; }
    else return;
    float4 v[CVT_CHUNK];
#pragma unroll
    for (int c = 0; c < CVT_CHUNK; c++) v[c] = ((const float4*)src)[off + c];
#pragma unroll
    for (int c = 0; c < CVT_CHUNK; c++) {
        __half h[4] = {__float2half_rn(v[c].x), __float2half_rn(v[c].y),
                       __float2half_rn(v[c].z), __float2half_rn(v[c].w)};
        *(uint2*)(dst + (size_t)(off + c) * 4) = *(uint2*)h;
    }
}

// ---------------------------------------------------------------------------
extern "C" void kernel_launch(void* const* d_in, const int* in_sizes, int n_in,
                              void* d_out, int out_size) {
    const float* x      = (const float*)d_in[0];
    const float* W      = (const float*)d_in[1];
    const float* W_res  = (const float*)d_in[2];
    const float* gamma  = (const float*)d_in[3];
    const float* beta   = (const float*)d_in[4];
    const float* Acoeff = (const float*)d_in[5];
    const float* Bbasis = (const float*)d_in[6];
    float* out = (float*)d_out;

    __half *xh; cudaGetSymbolAddress((void**)&xh, g_xh);
    __half *wh; cudaGetSymbolAddress((void**)&wh, g_wh);
    __half *rh; cudaGetSymbolAddress((void**)&rh, g_rh);

    cudaFuncSetAttribute(gemm_fused_kernel,
                         cudaFuncAttributeMaxDynamicSharedMemorySize, SM_TOTAL);

    int nx4 = (M_TOT * K_DIM) / 4;
    int nw4 = (D_DIM * K_DIM) / 4;
    int cvt_blocks = ((nx4 + 2 * nw4) / CVT_CHUNK + 255) / 256;
    aux_kernel<<<cvt_blocks + PREP_BLKS, 256>>>(x, W, W_res, gamma, beta,
                                                Bbasis, Acoeff, nx4, nw4);

    dim3 grid(D_DIM / BN, 2 * M_TOT / BM);   // (16, 256): y<128 stats, y>=128 residual
    gemm_fused_kernel<<<grid, NTHR, SM_TOTAL>>>(xh, wh, rh, out);
}

// round 17
// speedup vs baseline: 1.0537x; 1.0032x over previous
#include <cuda_runtime.h>
#include <cuda_fp16.h>
#include <cstdint>

#define M_TOT 16384
#define K_DIM 2048
#define D_DIM 2048
#define BASIS 64
#define EPSV  1e-5f

#define BM     128
#define BN     128
#define BK     64
#define STAGES 3
#define NKT    (K_DIM / BK)    // 32
#define NTHR   256
#define NSTATS 2048            // # stats CTAs

// ---------------- scratch (__device__ globals) ------------------------------
__device__ __half g_xh[(size_t)M_TOT * K_DIM];   // 64MB
__device__ __half g_wh[(size_t)D_DIM * K_DIM];   // 8MB
__device__ __half g_rh[(size_t)D_DIM * K_DIM];   // 8MB
__device__ float  g_At[BASIS * D_DIM];
__device__ float  g_gb[BASIS * D_DIM];           // gamma[d]*B[j][d]
__device__ float  g_c1[BASIS], g_c2[BASIS];
__device__ float  g_sum[M_TOT], g_sum2[M_TOT], g_dotb[M_TOT];
__device__ int    g_done;

// ---------------- PTX helpers ----------------------------------------------
__device__ __forceinline__ uint32_t smem_u32(const void* p) {
    uint32_t a;
    asm("{ .reg .u64 t; cvta.to.shared.u64 t, %1; cvt.u32.u64 %0, t; }" : "=r"(a) : "l"(p));
    return a;
}
__device__ __forceinline__ void cp_async16(uint32_t dst, const void* src) {
    asm volatile("cp.async.cg.shared.global [%0], [%1], 16;" :: "r"(dst), "l"(src));
}
__device__ __forceinline__ void cp_commit() {
    asm volatile("cp.async.commit_group;" ::: "memory");
}
template <int N>
__device__ __forceinline__ void cp_wait() {
    asm volatile("cp.async.wait_group %0;" :: "n"(N) : "memory");
}
// Non-volatile: ordering via data deps + __syncthreads memory clobbers.
__device__ __forceinline__ void ldsm4(uint32_t& r0, uint32_t& r1, uint32_t& r2,
                                      uint32_t& r3, uint32_t addr) {
    asm("ldmatrix.sync.aligned.m8n8.x4.shared.b16 {%0,%1,%2,%3}, [%4];"
        : "=r"(r0), "=r"(r1), "=r"(r2), "=r"(r3) : "r"(addr));
}
__device__ __forceinline__ void mma16816(float* d, uint32_t a0, uint32_t a1,
                                         uint32_t a2, uint32_t a3,
                                         uint32_t b0, uint32_t b1) {
    asm volatile("mma.sync.aligned.m16n8k16.row.col.f32.f16.f16.f32 "
                 "{%0,%1,%2,%3}, {%4,%5,%6,%7}, {%8,%9}, {%0,%1,%2,%3};"
                 : "+f"(d[0]), "+f"(d[1]), "+f"(d[2]), "+f"(d[3])
                 : "r"(a0), "r"(a1), "r"(a2), "r"(a3), "r"(b0), "r"(b1));
}

__device__ __forceinline__ float row_scalar(int row) {
    float mean = g_sum[row] * (1.0f / D_DIM);
    float var  = g_sum2[row] * (1.0f / D_DIM) - mean * mean;
    float inv  = rsqrtf(var + EPSV);
    int j = row & (BASIS - 1);
    return inv * (g_dotb[row] - mean * g_c1[j]) + g_c2[j];
}

#define STAGE_BYTES (BM * 128 + BN * 128)           // 32768
#define SM_STATS    (STAGES * STAGE_BYTES)          // 98304
#define SM_TOTAL    (STAGES * STAGE_BYTES + 1536)   // 99840  (x2 CTAs = 195KB)

// ---------------------------------------------------------------------------
// Unified dual GEMM, one launch. grid (16, 256).
// blockIdx.y < 128  -> stats path; blockIdx.y >= 128 -> residual path.
// 2 CTAs/SM, 256 thr, 8 warps, warp tile 64x32. Single barrier per kt.
// cp.async addressing hoisted: ch = tid&7 and r&7 are kt/i-invariant, so the
// swizzle offset is a loop constant; src/dst advance by fixed strides.
// ---------------------------------------------------------------------------
__global__ void __launch_bounds__(NTHR, 2)
gemm_fused_kernel(const __half* __restrict__ X, const __half* __restrict__ Wh,
                  const __half* __restrict__ Rh, float* __restrict__ out) {
    extern __shared__ char smem[];
    const uint32_t sb = smem_u32(smem);
    float* sst = (float*)(smem + SM_STATS);
    const int tid  = threadIdx.x;
    const int wid  = tid >> 5;
    const int lane = tid & 31;
    const int wm   = wid >> 2;           // 0..1 -> 64 rows
    const int wn   = wid & 3;            // 0..3 -> 32 cols
    const int stats = blockIdx.y < 128;
    const int m0   = (stats ? blockIdx.y : blockIdx.y - 128) * BM;
    const int n0   = blockIdx.x * BN;
    const __half* Bmat = stats ? Wh : Rh;

    if (stats && tid < 128) {
        sst[tid * 3] = 0.f; sst[tid * 3 + 1] = 0.f; sst[tid * 3 + 2] = 0.f;
    }

    // Hoisted load addressing: seg = tid + i*256 -> r = r0 + 32*i, ch = tid&7,
    // r&7 == r0&7, so swizzled dst offset is i-invariant modulo a fixed stride.
    const int r0 = tid >> 3;             // 0..31
    const int ch = tid & 7;
    const __half* srcA = X    + (size_t)(m0 + r0) * K_DIM + ch * 8;
    const __half* srcB = Bmat + (size_t)(n0 + r0) * K_DIM + ch * 8;
    const uint32_t dstOff = (uint32_t)(r0 * 128 + ((ch ^ (r0 & 7)) << 4));

    auto load_stage = [&](int stage, int kt) {
        const uint32_t base = sb + stage * STAGE_BYTES + dstOff;
        const __half* sA = srcA + kt * BK;
        const __half* sB = srcB + kt * BK;
#pragma unroll
        for (int i = 0; i < 4; i++)      // A: rows r0 + 32*i
            cp_async16(base + i * (32 * 128), sA + (size_t)i * 32 * K_DIM);
#pragma unroll
        for (int i = 0; i < 4; i++)      // B: rows r0 + 32*i
            cp_async16(base + BM * 128 + i * (32 * 128), sB + (size_t)i * 32 * K_DIM);
        cp_commit();
    };

    float acc[4][4][4];
#pragma unroll
    for (int i = 0; i < 4; i++)
#pragma unroll
        for (int j = 0; j < 4; j++)
#pragma unroll
            for (int q = 0; q < 4; q++) acc[i][j][q] = 0.f;

#pragma unroll
    for (int s = 0; s < STAGES - 1; s++) load_stage(s, s);

    for (int kt = 0; kt < NKT; kt++) {
        cp_wait<STAGES - 2>();
        __syncthreads();                 // single barrier per kt (3-stage WAR safe)

        int tn = kt + STAGES - 1;
        if (tn < NKT) load_stage(tn % STAGES, tn);
        else          cp_commit();

        const uint32_t stA = sb + (kt % STAGES) * STAGE_BYTES;
        const uint32_t stB = stA + BM * 128;

#pragma unroll
        for (int s = 0; s < 4; s++) {
            uint32_t a[4][4];
#pragma unroll
            for (int mt = 0; mt < 4; mt++) {
                int r  = wm * 64 + mt * 16 + (lane & 15);
                int c2 = 2 * s + (lane >> 4);
                ldsm4(a[mt][0], a[mt][1], a[mt][2], a[mt][3],
                      stA + r * 128 + ((c2 ^ (r & 7)) << 4));
            }
            uint32_t b[2][4];
#pragma unroll
            for (int nt = 0; nt < 2; nt++) {
                int r  = wn * 32 + nt * 16 + (lane & 7) + ((lane >> 4) << 3);
                int c2 = 2 * s + ((lane >> 3) & 1);
                ldsm4(b[nt][0], b[nt][1], b[nt][2], b[nt][3],
                      stB + r * 128 + ((c2 ^ (r & 7)) << 4));
            }
#pragma unroll
            for (int mt = 0; mt < 4; mt++)
#pragma unroll
                for (int nt = 0; nt < 2; nt++) {
                    mma16816(acc[mt][2 * nt],     a[mt][0], a[mt][1], a[mt][2], a[mt][3],
                             b[nt][0], b[nt][1]);
                    mma16816(acc[mt][2 * nt + 1], a[mt][0], a[mt][1], a[mt][2], a[mt][3],
                             b[nt][2], b[nt][3]);
                }
        }
    }

    if (!stats) {
        // wait for all stats CTAs (they were dispatched first; ~0 spin)
        if (tid == 0) {
            while (atomicAdd(&g_done, 0) < NSTATS) { }
            __threadfence();
        }
        __syncthreads();
#pragma unroll
        for (int mt = 0; mt < 4; mt++) {
            int row  = m0 + wm * 64 + mt * 16 + (lane >> 2);
            int col0 = n0 + wn * 32 + (lane & 3) * 2;
            float sc0 = row_scalar(row);
            float sc1 = row_scalar(row + 8);
            const float* at0 = g_At + (size_t)(row & (BASIS - 1)) * D_DIM + col0;
            const float* at1 = g_At + (size_t)((row + 8) & (BASIS - 1)) * D_DIM + col0;
#pragma unroll
            for (int j = 0; j < 4; j++) {
                float2 v0 = make_float2(acc[mt][j][0] + sc0 * at0[j * 8],
                                        acc[mt][j][1] + sc0 * at0[j * 8 + 1]);
                float2 v1 = make_float2(acc[mt][j][2] + sc1 * at1[j * 8],
                                        acc[mt][j][3] + sc1 * at1[j * 8 + 1]);
                *(float2*)(out + (size_t)row * D_DIM + col0 + j * 8)       = v0;
                *(float2*)(out + (size_t)(row + 8) * D_DIM + col0 + j * 8) = v1;
            }
        }
    } else {
        // stats path: per-row partials Σt, Σt², Σ t*gb
        __syncthreads();
#pragma unroll
        for (int mt = 0; mt < 4; mt++)
#pragma unroll
            for (int h = 0; h < 2; h++) {
                int rloc = wm * 64 + mt * 16 + (lane >> 2) + h * 8;
                int j64  = (m0 + rloc) & (BASIS - 1);
                const float* gbrow = g_gb + (size_t)j64 * D_DIM + n0 + wn * 32 + (lane & 3) * 2;
                float s = 0.f, s2 = 0.f, sbv = 0.f;
#pragma unroll
                for (int j = 0; j < 4; j++) {
                    float v0 = acc[mt][j][2 * h], v1 = acc[mt][j][2 * h + 1];
                    float gb0 = gbrow[j * 8], gb1 = gbrow[j * 8 + 1];
                    s  += v0 + v1;
                    s2 += v0 * v0 + v1 * v1;
                    sbv += v0 * gb0 + v1 * gb1;
                }
#pragma unroll
                for (int o = 1; o <= 2; o <<= 1) {
                    s   += __shfl_xor_sync(0xffffffffu, s, o);
                    s2  += __shfl_xor_sync(0xffffffffu, s2, o);
                    sbv += __shfl_xor_sync(0xffffffffu, sbv, o);
                }
                if ((lane & 3) == 0) {
                    atomicAdd(&sst[rloc * 3 + 0], s);
                    atomicAdd(&sst[rloc * 3 + 1], s2);
                    atomicAdd(&sst[rloc * 3 + 2], sbv);
                }
            }
        __syncthreads();
        if (tid < BM) {
            atomicAdd(&g_sum [m0 + tid], sst[tid * 3 + 0]);
            atomicAdd(&g_sum2[m0 + tid], sst[tid * 3 + 1]);
            atomicAdd(&g_dotb[m0 + tid], sst[tid * 3 + 2]);
            __threadfence();
        }
        __syncthreads();
        if (tid == 0) atomicAdd(&g_done, 1);
    }
}

// ---------------------------------------------------------------------------
// Single aux kernel: blocks [0,64) do prep (gb/c1/c2/At transpose);
// blocks >= 64 do x/W/W_res conversion (MLP=4) + stats/g_done zeroing.
#define CVT_CHUNK 4
#define PREP_BLKS 64
__global__ void __launch_bounds__(256)
aux_kernel(const float* __restrict__ x, const float* __restrict__ W,
           const float* __restrict__ R,
           const float* __restrict__ gamma, const float* __restrict__ beta,
           const float* __restrict__ Bb, const float* __restrict__ Acoeff,
           int nx4, int nw4) {
    const int tid = threadIdx.x;
    if (blockIdx.x < PREP_BLKS) {
        // ---- prep path ----
        __shared__ float sh1[8], sh2[8];
        const int j = blockIdx.x;
        float c1 = 0.f, c2 = 0.f;
        for (int d = tid; d < D_DIM; d += 256) {
            float b  = Bb[j * D_DIM + d];
            float gb = gamma[d] * b;
            g_gb[j * D_DIM + d] = gb;
            c1 += gb;
            c2 += beta[d] * b;
            g_At[j * D_DIM + d] = Acoeff[d * BASIS + j];
        }
#pragma unroll
        for (int o = 16; o > 0; o >>= 1) {
            c1 += __shfl_xor_sync(0xffffffffu, c1, o);
            c2 += __shfl_xor_sync(0xffffffffu, c2, o);
        }
        int lane = tid & 31, w = tid >> 5;
        if (lane == 0) { sh1[w] = c1; sh2[w] = c2; }
        __syncthreads();
        if (tid == 0) {
            float t1 = 0.f, t2 = 0.f;
#pragma unroll
            for (int i = 0; i < 8; i++) { t1 += sh1[i]; t2 += sh2[i]; }
            g_c1[j] = t1; g_c2[j] = t2;
        }
        return;
    }
    // ---- convert path ----
    int idx = (blockIdx.x - PREP_BLKS) * blockDim.x + tid;
    if (idx < M_TOT) { g_sum[idx] = 0.f; g_sum2[idx] = 0.f; g_dotb[idx] = 0.f; }
    if (idx == 0) g_done = 0;
    int base = idx * CVT_CHUNK;
    const float* src; __half* dst; int off;
    if (base < nx4)                { src = x; dst = g_xh; off = base; }
    else if (base < nx4 + nw4)     { src = W; dst = g_wh; off = base - nx4; }
    else if (base < nx4 + 2 * nw4) { src = R; dst = g_rh; off = base - nx4 - nw4; }
    else return;
    float4 v[CVT_CHUNK];
#pragma unroll
    for (int c = 0; c < CVT_CHUNK; c++) v[c] = ((const float4*)src)[off + c];
#pragma unroll
    for (int c = 0; c < CVT_CHUNK; c++) {
        __half h[4] = {__float2half_rn(v[c].x), __float2half_rn(v[c].y),
                       __float2half_rn(v[c].z), __float2half_rn(v[c].w)};
        *(uint2*)(dst + (size_t)(off + c) * 4) = *(uint2*)h;
    }
}

// ---------------------------------------------------------------------------
extern "C" void kernel_launch(void* const* d_in, const int* in_sizes, int n_in,
                              void* d_out, int out_size) {
    const float* x      = (const float*)d_in[0];
    const float* W      = (const float*)d_in[1];
    const float* W_res  = (const float*)d_in[2];
    const float* gamma  = (const float*)d_in[3];
    const float* beta   = (const float*)d_in[4];
    const float* Acoeff = (const float*)d_in[5];
    const float* Bbasis = (const float*)d_in[6];
    float* out = (float*)d_out;

    __half *xh; cudaGetSymbolAddress((void**)&xh, g_xh);
    __half *wh; cudaGetSymbolAddress((void**)&wh, g_wh);
    __half *rh; cudaGetSymbolAddress((void**)&rh, g_rh);

    cudaFuncSetAttribute(gemm_fused_kernel,
                         cudaFuncAttributeMaxDynamicSharedMemorySize, SM_TOTAL);

    int nx4 = (M_TOT * K_DIM) / 4;
    int nw4 = (D_DIM * K_DIM) / 4;
    int cvt_blocks = ((nx4 + 2 * nw4) / CVT_CHUNK + 255) / 256;
    aux_kernel<<<cvt_blocks + PREP_BLKS, 256>>>(x, W, W_res, gamma, beta,
                                                Bbasis, Acoeff, nx4, nw4);

    dim3 grid(D_DIM / BN, 2 * M_TOT / BM);   // (16, 256): y<128 stats, y>=128 residual
    gemm_fused_kernel<<<grid, NTHR, SM_TOTAL>>>(xh, wh, rh, out);
}